// round 5
// baseline (speedup 1.0000x reference)
#include <cuda_runtime.h>
#include <cstdint>

#define N_ENT 50000
#define R_REL 16
#define D_EMB 64
#define F_IN  128
#define E_EDGE 100000
#define NEDGE (R_REL * E_EDGE)          // 1.6M
#define NK (N_ENT * R_REL)              // 800000 keys (row*16 + rel)
#define KTOT (R_REL * D_EMB)            // 1024
#define NL 2

// ---------------- scratch (device globals; allocation-free rule) ------------
__device__ float g_emb[(size_t)N_ENT * D_EMB];                 // 12.8 MB (L2-hot)
__device__ float g_stack[(size_t)N_ENT * KTOT];                // 204.8 MB (stream-only)
__device__ float g_Wcat[NL * KTOT * D_EMB];                    // 512 KB
__device__ int   g_counts[NK];
__device__ int   g_rowstart[NK + 1];
__device__ int   g_cursor[NK];
__device__ int2  g_recs[NEDGE];        // {(r<<16)|col, val bits}, sorted by row,rel

#define SCHUNK 1024
#define NCH ((NK + SCHUNK - 1) / SCHUNK)                       // 782
__device__ int   g_part[NCH];

// ---------------------------------------------------------------------------
// Input GEMM: g_emb[n,d] = sum_k x[n,k] * ent_emb[k,d]   (K=128)  (proven)
// ---------------------------------------------------------------------------
#define KS_IN 132

__global__ void k_input_gemm(const float* __restrict__ x,
                             const float* __restrict__ ent_emb,
                             int nrows) {
    extern __shared__ float smem[];
    float* sA  = smem;
    float* sBt = smem + 64 * KS_IN;

    const int tid  = threadIdx.x;
    const int base = blockIdx.x * 64;

    for (int idx = tid; idx < F_IN * D_EMB; idx += 256) {
        int k = idx / D_EMB, d = idx % D_EMB;
        sBt[d * KS_IN + k] = ent_emb[idx];
    }
    for (int idx4 = tid; idx4 < 64 * (F_IN / 4); idx4 += 256) {
        int row = idx4 / (F_IN / 4), kq = idx4 % (F_IN / 4);
        float4 v = make_float4(0.f, 0.f, 0.f, 0.f);
        if (base + row < nrows)
            v = reinterpret_cast<const float4*>(x + (size_t)(base + row) * F_IN)[kq];
        *reinterpret_cast<float4*>(&sA[row * KS_IN + kq * 4]) = v;
    }
    __syncthreads();

    const int cs = tid & 15;
    const int rs = tid >> 4;
    float acc[4][4];
#pragma unroll
    for (int i = 0; i < 4; i++)
#pragma unroll
        for (int j = 0; j < 4; j++) acc[i][j] = 0.f;

#pragma unroll 8
    for (int kq = 0; kq < F_IN / 4; kq++) {
        float4 a[4], b[4];
#pragma unroll
        for (int i = 0; i < 4; i++)
            a[i] = *reinterpret_cast<const float4*>(&sA[(rs + 16 * i) * KS_IN + kq * 4]);
#pragma unroll
        for (int j = 0; j < 4; j++)
            b[j] = *reinterpret_cast<const float4*>(&sBt[(cs + 16 * j) * KS_IN + kq * 4]);
#pragma unroll
        for (int i = 0; i < 4; i++)
#pragma unroll
            for (int j = 0; j < 4; j++)
                acc[i][j] += a[i].x * b[j].x + a[i].y * b[j].y +
                             a[i].z * b[j].z + a[i].w * b[j].w;
    }

#pragma unroll
    for (int i = 0; i < 4; i++) {
        int row = base + rs + 16 * i;
        if (row < nrows) {
#pragma unroll
            for (int j = 0; j < 4; j++)
                g_emb[(size_t)row * D_EMB + cs + 16 * j] = acc[i][j];
        }
    }
}

// ---------------------------------------------------------------------------
// CSR build over keys = row*16 + rel  (round-3 proven)
// ---------------------------------------------------------------------------
__global__ void k_zero_counts() {
    int i = blockIdx.x * blockDim.x + threadIdx.x;
    if (i < NK / 4)
        reinterpret_cast<int4*>(g_counts)[i] = make_int4(0, 0, 0, 0);
}

__global__ void k_hist(const int* __restrict__ erow) {
    int i = blockIdx.x * blockDim.x + threadIdx.x;
    if (i >= NEDGE) return;
    int r = i / E_EDGE;
    atomicAdd(&g_counts[__ldg(erow + i) * R_REL + r], 1);
}

__global__ void k_scan1() {
    __shared__ int ss[256];
    int b = blockIdx.x, t = threadIdx.x;
    int base = b * SCHUNK + t * 4;
    int4 c = make_int4(0, 0, 0, 0);
    if (base < NK) c = *reinterpret_cast<const int4*>(&g_counts[base]);
    int s = c.x + c.y + c.z + c.w;
    ss[t] = s;
    __syncthreads();
    for (int off = 1; off < 256; off <<= 1) {
        int v = (t >= off) ? ss[t - off] : 0;
        __syncthreads();
        ss[t] += v;
        __syncthreads();
    }
    int excl = ss[t] - s;
    if (t == 255) g_part[b] = ss[t];
    if (base < NK) {
        int r = excl;
        g_rowstart[base + 0] = r; r += c.x;
        g_rowstart[base + 1] = r; r += c.y;
        g_rowstart[base + 2] = r; r += c.z;
        g_rowstart[base + 3] = r;
    }
}

__global__ void k_scan2() {
    __shared__ int sp[1024];
    int t = threadIdx.x;
    int v = (t < NCH) ? g_part[t] : 0;
    sp[t] = v;
    __syncthreads();
    for (int off = 1; off < 1024; off <<= 1) {
        int x = (t >= off) ? sp[t - off] : 0;
        __syncthreads();
        sp[t] += x;
        __syncthreads();
    }
    if (t < NCH) g_part[t] = sp[t] - v;
    if (t == 1023) g_rowstart[NK] = sp[1023];
}

__global__ void k_scan3() {
    int i = blockIdx.x * blockDim.x + threadIdx.x;
    if (i < NK) {
        int v = g_rowstart[i] + g_part[i >> 10];
        g_rowstart[i] = v;
        g_cursor[i] = v;
    }
}

__global__ void k_place(const int* __restrict__ erow,
                        const int* __restrict__ ecol,
                        const float* __restrict__ eval) {
    int i = blockIdx.x * blockDim.x + threadIdx.x;
    if (i >= NEDGE) return;
    int r = i / E_EDGE;
    int key = __ldg(erow + i) * R_REL + r;
    int pos = atomicAdd(&g_cursor[key], 1);
    g_recs[pos] = make_int2((r << 16) | __ldg(ecol + i),
                            __float_as_int(__ldg(eval + i)));
}

// ---------------------------------------------------------------------------
// Wcat[l][(r*64+e)*64 + d] = rel_trans[l][r][d][e]  (proven)
// ---------------------------------------------------------------------------
__global__ void k_wcat(const float* __restrict__ rel_trans) {
    int i = blockIdx.x * blockDim.x + threadIdx.x;
    if (i >= NL * R_REL * D_EMB * D_EMB) return;
    int e = i & 63;
    int d = (i >> 6) & 63;
    int r = (i >> 12) & 15;
    int l = i >> 16;
    g_Wcat[l * (KTOT * D_EMB) + ((r << 6) + e) * D_EMB + d] = rel_trans[i];
}

// ---------------------------------------------------------------------------
// Gather into stack: one WARP per destination row (avg degree 32).
// recs for a row are rel-sorted; accumulate each rel-run in 2 regs,
// flush to per-warp smem slice, write 4KB stack row coalesced.
// Random reads hit only g_emb (12.8MB, L2-resident). No atomics.
// ---------------------------------------------------------------------------
__global__ void __launch_bounds__(256)
k_gather_stack() {
    __shared__ float sacc[8][KTOT];          // 32 KB
    const int wid  = threadIdx.x >> 5;
    const int lane = threadIdx.x & 31;
    const int row  = blockIdx.x * 8 + wid;
    if (row >= N_ENT) return;
    float* sa = sacc[wid];

    // zero slice: 1024 floats = 256 float4, 8 per lane
#pragma unroll
    for (int i = 0; i < 8; i++)
        *reinterpret_cast<float4*>(&sa[(lane + i * 32) * 4]) =
            make_float4(0.f, 0.f, 0.f, 0.f);

    const int s = __ldg(&g_rowstart[row * R_REL]);
    const int e = __ldg(&g_rowstart[(row + 1) * R_REL]);

    int rcur = -1;
    float ax = 0.f, ay = 0.f;
    for (int j = s; j < e; j++) {
        int2 rec = __ldg(&g_recs[j]);
        int r = rec.x >> 16;
        if (r != rcur) {                      // warp-uniform branch
            if (rcur >= 0) {
                sa[rcur * 64 + lane * 2]     = ax;
                sa[rcur * 64 + lane * 2 + 1] = ay;
            }
            rcur = r; ax = 0.f; ay = 0.f;
        }
        float v = __int_as_float(rec.y);
        float2 p = *reinterpret_cast<const float2*>(
            &g_emb[(size_t)(rec.x & 0xFFFF) * D_EMB + lane * 2]);
        ax = fmaf(v, p.x, ax);
        ay = fmaf(v, p.y, ay);
    }
    if (rcur >= 0) {
        sa[rcur * 64 + lane * 2]     = ax;
        sa[rcur * 64 + lane * 2 + 1] = ay;
    }

    // write stack row (4KB) coalesced
    float* dst = &g_stack[(size_t)row * KTOT];
#pragma unroll
    for (int i = 0; i < 8; i++)
        *reinterpret_cast<float4*>(&dst[(lane + i * 32) * 4]) =
            *reinterpret_cast<const float4*>(&sa[(lane + i * 32) * 4]);
}

// ---------------------------------------------------------------------------
// Big GEMM + ReLU: g_emb[n,d] = relu( sum_k g_stack[n,k] * Wcat[l][k,d] )
// K=1024, BM=128, BK=64, 256 threads, 4x8 thread tile, fma.rn.f32x2.
// Device globals referenced IN KERNEL (round-2 lesson).  (round-3/4 proven)
// ---------------------------------------------------------------------------
#define BM 128
#define BK 64
#define SA_S 68
#define SB_S 68

__global__ void __launch_bounds__(256)
k_gemm_relu(int layer, int nrows) {
    extern __shared__ float sm[];
    float* sA = sm;                 // [BM][SA_S]
    float* sB = sm + BM * SA_S;     // [BK][SB_S]

    const float* A = g_stack;
    const float* B = g_Wcat + (size_t)layer * KTOT * D_EMB;
    float* C       = g_emb;

    const int tid  = threadIdx.x;
    const int base = blockIdx.x * BM;
    const int tr = tid >> 3;
    const int tc = tid & 7;

    unsigned long long acc[4][4];
#pragma unroll
    for (int i = 0; i < 4; i++)
#pragma unroll
        for (int j = 0; j < 4; j++) acc[i][j] = 0ull;

    for (int kc = 0; kc < KTOT; kc += BK) {
#pragma unroll
        for (int i = 0; i < 8; i++) {
            int idx4 = tid + i * 256;
            int row = idx4 >> 4;
            int kq  = idx4 & 15;
            float4 v = make_float4(0.f, 0.f, 0.f, 0.f);
            if (base + row < nrows)
                v = *reinterpret_cast<const float4*>(
                    &A[(size_t)(base + row) * KTOT + kc + kq * 4]);
            *reinterpret_cast<float4*>(&sA[row * SA_S + kq * 4]) = v;
        }
#pragma unroll
        for (int i = 0; i < 4; i++) {
            int idx4 = tid + i * 256;
            int k  = idx4 >> 4;
            int dq = idx4 & 15;
            *reinterpret_cast<float4*>(&sB[k * SB_S + dq * 4]) =
                *reinterpret_cast<const float4*>(&B[(size_t)(kc + k) * D_EMB + dq * 4]);
        }
        __syncthreads();

#pragma unroll
        for (int k4 = 0; k4 < BK; k4 += 4) {
            float4 av[4];
#pragma unroll
            for (int i = 0; i < 4; i++)
                av[i] = *reinterpret_cast<const float4*>(&sA[(tr * 4 + i) * SA_S + k4]);
#pragma unroll
            for (int kk = 0; kk < 4; kk++) {
                int k = k4 + kk;
                ulonglong2 b01 = *reinterpret_cast<const ulonglong2*>(&sB[k * SB_S + tc * 8]);
                ulonglong2 b23 = *reinterpret_cast<const ulonglong2*>(&sB[k * SB_S + tc * 8 + 4]);
                unsigned long long bp0 = b01.x, bp1 = b01.y, bp2 = b23.x, bp3 = b23.y;
#pragma unroll
                for (int i = 0; i < 4; i++) {
                    float a = (kk == 0) ? av[i].x : (kk == 1) ? av[i].y
                             : (kk == 2) ? av[i].z : av[i].w;
                    unsigned long long a2;
                    asm("mov.b64 %0, {%1, %1};" : "=l"(a2) : "f"(a));
                    asm("fma.rn.f32x2 %0, %1, %2, %0;" : "+l"(acc[i][0]) : "l"(a2), "l"(bp0));
                    asm("fma.rn.f32x2 %0, %1, %2, %0;" : "+l"(acc[i][1]) : "l"(a2), "l"(bp1));
                    asm("fma.rn.f32x2 %0, %1, %2, %0;" : "+l"(acc[i][2]) : "l"(a2), "l"(bp2));
                    asm("fma.rn.f32x2 %0, %1, %2, %0;" : "+l"(acc[i][3]) : "l"(a2), "l"(bp3));
                }
            }
        }
        __syncthreads();
    }

#pragma unroll
    for (int i = 0; i < 4; i++) {
        int row = base + tr * 4 + i;
        if (row < nrows) {
#pragma unroll
            for (int j = 0; j < 4; j++) {
                float2 v = *reinterpret_cast<float2*>(&acc[i][j]);
                v.x = fmaxf(v.x, 0.f);
                v.y = fmaxf(v.y, 0.f);
                *reinterpret_cast<float2*>(
                    &C[(size_t)row * D_EMB + tc * 8 + j * 2]) = v;
            }
        }
    }
}

// ---------------------------------------------------------------------------
// L2 normalize rows
// ---------------------------------------------------------------------------
__global__ void k_normalize(float* __restrict__ out) {
    int row  = blockIdx.x * 8 + (threadIdx.x >> 5);
    int lane = threadIdx.x & 31;
    if (row >= N_ENT) return;
    const float* e = g_emb + (size_t)row * D_EMB;
    float v0 = e[lane], v1 = e[lane + 32];
    float ss = v0 * v0 + v1 * v1;
#pragma unroll
    for (int o = 16; o > 0; o >>= 1) ss += __shfl_xor_sync(0xFFFFFFFFu, ss, o);
    float s = 1.0f / fmaxf(sqrtf(ss), 1e-12f);
    out[(size_t)row * D_EMB + lane]      = v0 * s;
    out[(size_t)row * D_EMB + lane + 32] = v1 * s;
}

// ---------------------------------------------------------------------------
extern "C" void kernel_launch(void* const* d_in, const int* in_sizes, int n_in,
                              void* d_out, int out_size) {
    const float* x         = (const float*)d_in[0];
    const float* ent_emb   = (const float*)d_in[1];
    const float* rel_trans = (const float*)d_in[2];
    const int*   erow      = (const int*)d_in[3];
    const int*   ecol      = (const int*)d_in[4];
    const float* eval      = (const float*)d_in[5];
    float* out             = (float*)d_out;

    const int in_blocks    = (N_ENT + 63) / 64;          // 782
    const int gemm_blocks  = (N_ENT + BM - 1) / BM;      // 391
    const int edge_blocks  = (NEDGE + 255) / 256;        // 6250
    const int row_warps    = (N_ENT + 7) / 8;            // 6250

    const size_t smem_in   = 2 * 64 * KS_IN * sizeof(float);
    const size_t smem_gemm = (BM * SA_S + BK * SB_S) * sizeof(float);  // 52224
    cudaFuncSetAttribute(k_input_gemm,
                         cudaFuncAttributeMaxDynamicSharedMemorySize, (int)smem_in);
    cudaFuncSetAttribute(k_gemm_relu,
                         cudaFuncAttributeMaxDynamicSharedMemorySize, (int)smem_gemm);

    k_input_gemm<<<in_blocks, 256, smem_in>>>(x, ent_emb, N_ENT);
    k_zero_counts<<<(NK / 4 + 255) / 256, 256>>>();
    k_hist<<<edge_blocks, 256>>>(erow);
    k_scan1<<<NCH, 256>>>();
    k_scan2<<<1, 1024>>>();
    k_scan3<<<(NK + 255) / 256, 256>>>();
    k_place<<<edge_blocks, 256>>>(erow, ecol, eval);
    k_wcat<<<(NL * R_REL * D_EMB * D_EMB + 255) / 256, 256>>>(rel_trans);

    for (int l = 0; l < NL; l++) {
        k_gather_stack<<<row_warps, 256>>>();
        k_gemm_relu<<<gemm_blocks, 256, smem_gemm>>>(l, N_ENT);
    }

    k_normalize<<<row_warps, 256>>>(out);
}

// round 7
// speedup vs baseline: 1.9283x; 1.9283x over previous
#include <cuda_runtime.h>
#include <cstdint>

#define N_ENT 50000
#define R_REL 16
#define D_EMB 64
#define F_IN  128
#define E_EDGE 100000
#define NL 2

// ---------------- scratch (device globals; allocation-free rule) ------------
__device__ float g_emb[(size_t)N_ENT * D_EMB];                 // 12.8 MB (L2-hot)
__device__ float g_acc[(size_t)N_ENT * D_EMB];                 // 12.8 MB (L2-hot)
__device__ float g_Y[(size_t)R_REL * N_ENT * D_EMB];           // 204.8 MB (stream)

// ---------------------------------------------------------------------------
// Input GEMM (round-1 proven): g_emb = x @ ent_emb  (K=128)
// ---------------------------------------------------------------------------
#define KS_IN 132

__global__ void k_input_gemm(const float* __restrict__ x,
                             const float* __restrict__ ent_emb,
                             int nrows) {
    extern __shared__ float smemf[];
    float* sA  = smemf;
    float* sBt = smemf + 64 * KS_IN;

    const int tid  = threadIdx.x;
    const int base = blockIdx.x * 64;

    for (int idx = tid; idx < F_IN * D_EMB; idx += 256) {
        int k = idx / D_EMB, d = idx % D_EMB;
        sBt[d * KS_IN + k] = ent_emb[idx];
    }
    for (int idx4 = tid; idx4 < 64 * (F_IN / 4); idx4 += 256) {
        int row = idx4 / (F_IN / 4), kq = idx4 % (F_IN / 4);
        float4 v = make_float4(0.f, 0.f, 0.f, 0.f);
        if (base + row < nrows)
            v = reinterpret_cast<const float4*>(x + (size_t)(base + row) * F_IN)[kq];
        *reinterpret_cast<float4*>(&sA[row * KS_IN + kq * 4]) = v;
    }
    __syncthreads();

    const int cs = tid & 15;
    const int rs = tid >> 4;
    float acc[4][4];
#pragma unroll
    for (int i = 0; i < 4; i++)
#pragma unroll
        for (int j = 0; j < 4; j++) acc[i][j] = 0.f;

#pragma unroll 8
    for (int kq = 0; kq < F_IN / 4; kq++) {
        float4 a[4], b[4];
#pragma unroll
        for (int i = 0; i < 4; i++)
            a[i] = *reinterpret_cast<const float4*>(&sA[(rs + 16 * i) * KS_IN + kq * 4]);
#pragma unroll
        for (int j = 0; j < 4; j++)
            b[j] = *reinterpret_cast<const float4*>(&sBt[(cs + 16 * j) * KS_IN + kq * 4]);
#pragma unroll
        for (int i = 0; i < 4; i++)
#pragma unroll
            for (int j = 0; j < 4; j++)
                acc[i][j] += a[i].x * b[j].x + a[i].y * b[j].y +
                             a[i].z * b[j].z + a[i].w * b[j].w;
    }

#pragma unroll
    for (int i = 0; i < 4; i++) {
        int row = base + rs + 16 * i;
        if (row < nrows) {
#pragma unroll
            for (int j = 0; j < 4; j++)
                g_emb[(size_t)row * D_EMB + cs + 16 * j] = acc[i][j];
        }
    }
}

// ---------------------------------------------------------------------------
// HMMA transform: Y[r][n][d] = sum_e emb[n][e] * W_r[d][e]
// mma.sync m16n8k16 bf16 (base compute_103 feature — tcgen05 is not emittable
// from this harness's PTX target, per round-6 failure).
// fp32 split: A=Ah+Al, W=Wh+Wl; Y = Ah*Wh + Ah*Wl + Al*Wh (fp32 accum).
// CTA: 256 threads, 128 rows x 64 cols, one relation (blockIdx.y).
// smem packing (32-bit words hold bf16x2):
//   A hi/lo: [row][epair]  stride AW=36 words  (bank = 4g+t, conflict-free)
//   B hi/lo: [kpair][d]    stride BW=68 words  (bank = 4t+g, conflict-free)
//   where Bp[kpair][d] packs (W[d][2k],W[d][2k+1]) = B[k][n] k-pairs.
// ---------------------------------------------------------------------------
#define AW 36
#define BW 68
#define SM_AH 0
#define SM_AL (128 * AW)
#define SM_BH (2 * 128 * AW)
#define SM_BL (2 * 128 * AW + 32 * BW)
#define SM_WORDS (2 * 128 * AW + 2 * 32 * BW)    // 13568 words = 54272 B

#define CVT_BF16X2(res, a, b) \
    asm("cvt.rn.satfinite.bf16x2.f32 %0, %1, %2;" : "=r"(res) : "f"(b), "f"(a))

__device__ __forceinline__ void split_pair(float2 f, uint32_t& h, uint32_t& l) {
    CVT_BF16X2(h, f.x, f.y);
    float h0 = __uint_as_float(h << 16);
    float h1 = __uint_as_float(h & 0xFFFF0000u);
    CVT_BF16X2(l, f.x - h0, f.y - h1);
}

#define MMA_BF16(c, a, b0, b1) \
    asm volatile("mma.sync.aligned.m16n8k16.row.col.f32.bf16.bf16.f32 " \
        "{%0,%1,%2,%3}, {%4,%5,%6,%7}, {%8,%9}, {%0,%1,%2,%3};" \
        : "+f"((c)[0]), "+f"((c)[1]), "+f"((c)[2]), "+f"((c)[3]) \
        : "r"((a)[0]), "r"((a)[1]), "r"((a)[2]), "r"((a)[3]), \
          "r"(b0), "r"(b1))

__global__ void __launch_bounds__(256)
k_transform_hmma(const float* __restrict__ rel_trans, int layer, int nrows) {
    extern __shared__ uint32_t sw[];
    uint32_t* sAh = sw + SM_AH;
    uint32_t* sAl = sw + SM_AL;
    uint32_t* sBh = sw + SM_BH;
    uint32_t* sBl = sw + SM_BL;

    const int tid  = threadIdx.x;
    const int base = blockIdx.x * 128;
    const int r    = blockIdx.y;
    const float* W = rel_trans + ((size_t)layer * R_REL + r) * (D_EMB * D_EMB);

    // Stage W: 64x64 f32 -> 2048 bf16x2 pairs; Bp[kpair=e>>1][d]
#pragma unroll
    for (int i = 0; i < 8; i++) {
        int p  = tid + i * 256;        // 0..2047
        int d  = p >> 5;               // 0..63
        int e2 = p & 31;               // kpair
        float2 f = *reinterpret_cast<const float2*>(W + d * 64 + e2 * 2);
        uint32_t h, l; split_pair(f, h, l);
        sBh[e2 * BW + d] = h;
        sBl[e2 * BW + d] = l;
    }
    // Stage A: 128 rows x 32 epairs
#pragma unroll
    for (int i = 0; i < 16; i++) {
        int p   = tid + i * 256;       // 0..4095
        int row = p >> 5;
        int e2  = p & 31;
        float2 f = make_float2(0.f, 0.f);
        if (base + row < nrows)
            f = *reinterpret_cast<const float2*>(
                g_emb + (size_t)(base + row) * D_EMB + e2 * 2);
        uint32_t h, l; split_pair(f, h, l);
        sAh[row * AW + e2] = h;
        sAl[row * AW + e2] = l;
    }
    __syncthreads();

    const int warp = tid >> 5;
    const int lane = tid & 31;
    const int g = lane >> 2;           // groupID
    const int t = lane & 3;            // threadID in group
    const int wrow = warp * 16;

    float acc[8][4];
#pragma unroll
    for (int j = 0; j < 8; j++)
#pragma unroll
        for (int q = 0; q < 4; q++) acc[j][q] = 0.f;

#pragma unroll
    for (int ks = 0; ks < 4; ks++) {
        const int r0 = (wrow + g) * AW;
        const int r1 = (wrow + g + 8) * AW;
        const int eb = ks * 8 + t;
        uint32_t ah[4], al[4];
        ah[0] = sAh[r0 + eb];     ah[1] = sAh[r1 + eb];
        ah[2] = sAh[r0 + eb + 4]; ah[3] = sAh[r1 + eb + 4];
        al[0] = sAl[r0 + eb];     al[1] = sAl[r1 + eb];
        al[2] = sAl[r0 + eb + 4]; al[3] = sAl[r1 + eb + 4];

        const int kb0 = (ks * 8 + t) * BW;
        const int kb1 = (ks * 8 + t + 4) * BW;
#pragma unroll
        for (int j = 0; j < 8; j++) {
            int n = j * 8 + g;
            uint32_t bh0 = sBh[kb0 + n], bh1 = sBh[kb1 + n];
            uint32_t bl0 = sBl[kb0 + n], bl1 = sBl[kb1 + n];
            MMA_BF16(acc[j], ah, bh0, bh1);
            MMA_BF16(acc[j], ah, bl0, bl1);
            MMA_BF16(acc[j], al, bh0, bh1);
        }
    }

    // Epilogue: D rows g (+8), cols n0 + 2t (+1)
    {
        int row0 = base + wrow + g;
        int row1 = row0 + 8;
        float* Yr = g_Y + (size_t)r * N_ENT * D_EMB;
#pragma unroll
        for (int j = 0; j < 8; j++) {
            int col = j * 8 + t * 2;
            if (row0 < nrows)
                *reinterpret_cast<float2*>(Yr + (size_t)row0 * D_EMB + col) =
                    make_float2(acc[j][0], acc[j][1]);
            if (row1 < nrows)
                *reinterpret_cast<float2*>(Yr + (size_t)row1 * D_EMB + col) =
                    make_float2(acc[j][2], acc[j][3]);
        }
    }
}

// ---------------------------------------------------------------------------
// Zero accumulator (round-1 proven)
// ---------------------------------------------------------------------------
__global__ void k_zero_acc() {
    int i = blockIdx.x * blockDim.x + threadIdx.x;
    if (i < N_ENT * D_EMB / 4)
        reinterpret_cast<float4*>(g_acc)[i] = make_float4(0.f, 0.f, 0.f, 0.f);
}

// ---------------------------------------------------------------------------
// Edge scatter (round-1 proven): acc[row] += val * Y[r][col] via red.global (L2)
// ---------------------------------------------------------------------------
__global__ void k_scatter(const int* __restrict__ erow,
                          const int* __restrict__ ecol,
                          const float* __restrict__ eval) {
    long long tt = (long long)blockIdx.x * blockDim.x + threadIdx.x;
    int seg = (int)(tt >> 4);
    if (seg >= R_REL * E_EDGE) return;
    int d4 = (int)(tt & 15);

    int row = __ldg(erow + seg);
    int col = __ldg(ecol + seg);
    float v = __ldg(eval + seg);
    int r   = seg / E_EDGE;

    float4 q = reinterpret_cast<const float4*>(
                   g_Y + ((size_t)r * N_ENT + col) * D_EMB)[d4];
    float* dst = g_acc + (size_t)row * D_EMB + d4 * 4;
    asm volatile("red.global.add.v4.f32 [%0], {%1,%2,%3,%4};"
                 :: "l"(dst), "f"(v * q.x), "f"(v * q.y),
                    "f"(v * q.z), "f"(v * q.w)
                 : "memory");
}

// ---------------------------------------------------------------------------
// ReLU (round-1 proven)
// ---------------------------------------------------------------------------
__global__ void k_relu() {
    int i = blockIdx.x * blockDim.x + threadIdx.x;
    if (i < N_ENT * D_EMB / 4) {
        float4 v = reinterpret_cast<const float4*>(g_acc)[i];
        v.x = fmaxf(v.x, 0.f); v.y = fmaxf(v.y, 0.f);
        v.z = fmaxf(v.z, 0.f); v.w = fmaxf(v.w, 0.f);
        reinterpret_cast<float4*>(g_emb)[i] = v;
    }
}

// ---------------------------------------------------------------------------
// L2 normalize rows (round-1 proven)
// ---------------------------------------------------------------------------
__global__ void k_normalize(float* __restrict__ out) {
    int row  = blockIdx.x * 8 + (threadIdx.x >> 5);
    int lane = threadIdx.x & 31;
    if (row >= N_ENT) return;
    const float* e = g_emb + (size_t)row * D_EMB;
    float v0 = e[lane], v1 = e[lane + 32];
    float ss = v0 * v0 + v1 * v1;
#pragma unroll
    for (int o = 16; o > 0; o >>= 1) ss += __shfl_xor_sync(0xFFFFFFFFu, ss, o);
    float s = 1.0f / fmaxf(sqrtf(ss), 1e-12f);
    out[(size_t)row * D_EMB + lane]      = v0 * s;
    out[(size_t)row * D_EMB + lane + 32] = v1 * s;
}

// ---------------------------------------------------------------------------
extern "C" void kernel_launch(void* const* d_in, const int* in_sizes, int n_in,
                              void* d_out, int out_size) {
    const float* x         = (const float*)d_in[0];
    const float* ent_emb   = (const float*)d_in[1];
    const float* rel_trans = (const float*)d_in[2];
    const int*   erow      = (const int*)d_in[3];
    const int*   ecol      = (const int*)d_in[4];
    const float* eval      = (const float*)d_in[5];
    float* out             = (float*)d_out;

    const int in_blocks      = (N_ENT + 63) / 64;             // 782
    const int tc_blocks      = (N_ENT + 127) / 128;           // 391
    const int elem_blocks    = (N_ENT * D_EMB / 4 + 255) / 256;
    const int scatter_blocks = (R_REL * E_EDGE * 16) / 256;   // 100000
    const int row_warps      = (N_ENT + 7) / 8;

    const size_t smem_in = 2 * 64 * KS_IN * sizeof(float);
    const size_t smem_t  = SM_WORDS * sizeof(uint32_t);       // 54272
    cudaFuncSetAttribute(k_input_gemm,
                         cudaFuncAttributeMaxDynamicSharedMemorySize, (int)smem_in);
    cudaFuncSetAttribute(k_transform_hmma,
                         cudaFuncAttributeMaxDynamicSharedMemorySize, (int)smem_t);

    k_input_gemm<<<in_blocks, 256, smem_in>>>(x, ent_emb, N_ENT);

    for (int l = 0; l < NL; l++) {
        k_transform_hmma<<<dim3(tc_blocks, R_REL), 256, smem_t>>>(
            rel_trans, l, N_ENT);
        k_zero_acc<<<elem_blocks, 256>>>();
        k_scatter<<<scatter_blocks, 256>>>(erow, ecol, eval);
        k_relu<<<elem_blocks, 256>>>();
    }

    k_normalize<<<row_warps, 256>>>(out);
}